// round 12
// baseline (speedup 1.0000x reference)
#include <cuda_runtime.h>

// Shapes fixed by the problem: [B=4, C=32, H=1024, W=1024] fp32 -> [B,H,W] fp32
#define CCH 32
#define HH  1024
#define WW  1024
#define RAD 25    // kernel_radius = W // 40 = 25 (window = 51)
#define RPB 2     // rows per block in kernel A
#define PAD 32    // zero-pad rows above/below each image in scratch (>= RAD+1)
#define HP  (HH + 2 * PAD)

// padded scratch: channel-summed + box-w'd intermediate, with zero halo rows
__device__ float g_scratch[4 * HP * WW];

__device__ __forceinline__ float sqrt_approx(float s) {
    float r;
    asm("sqrt.approx.f32 %0, %1;" : "=f"(r) : "f"(s));
    return r;   // sqrt.approx(0) = 0, no NaN guard needed
}

// L2 evict_last access policy (keeps scratch resident for kernel B)
__device__ __forceinline__ unsigned long long evict_last_policy() {
    unsigned long long pol;
    asm("createpolicy.fractional.L2::evict_last.b64 %0, 1.0;" : "=l"(pol));
    return pol;
}

// 128-bit store with L2 evict_last cache hint
__device__ __forceinline__ void st_evict_last4(float* p, float4 v, unsigned long long pol) {
    asm volatile("st.global.L2::cache_hint.v4.f32 [%0], {%1,%2,%3,%4}, %5;"
                 :: "l"(p), "f"(v.x), "f"(v.y), "f"(v.z), "f"(v.w), "l"(pol) : "memory");
}

// ---------------------------------------------------------------------------
// Kernel A (FROZEN — measured 86.7us, DRAM+LTS bound): per (b, 2-row tile),
// gradient magnitude, channel sum, box-w. 1-deep software pipeline,
// min-blocks=5 (~40 warps/SM), evict_last scratch stores, fused halo zeroing.
// ---------------------------------------------------------------------------
__global__ __launch_bounds__(256, 5) void grad_boxw_kernel(const float* __restrict__ x) {
    const int h0   = blockIdx.x * RPB;
    const int b    = blockIdx.y;
    const int tid  = threadIdx.x;
    const int lane = tid & 31;
    const int wid  = tid >> 5;
    const int w0   = tid << 2;

    const unsigned long long pol = evict_last_policy();

    // ---- fused halo zeroing ----
    if (blockIdx.x < 2 * PAD) {
        int row  = blockIdx.x;
        int prow = (row < PAD) ? row : (HH + row);
        st_evict_last4(g_scratch + ((size_t)b * HP + prow) * WW + 4 * tid,
                       make_float4(0.f, 0.f, 0.f, 0.f), pol);
    }

    const float* xb = x + (size_t)b * CCH * HH * WW;
    const bool has_top  = (h0 > 0);
    const bool has_left = (w0 > 0);

    float a00 = 0.f, a01 = 0.f, a02 = 0.f, a03 = 0.f;
    float a10 = 0.f, a11 = 0.f, a12 = 0.f, a13 = 0.f;

    // ---- prologue: loads for channel 0 ----
    const float* row0 = xb + (size_t)h0 * WW;
    const float* row1 = row0 + WW;
    float4 prev = has_top ? *reinterpret_cast<const float4*>(row0 - WW + w0)
                          : make_float4(0.f, 0.f, 0.f, 0.f);
    float4 c0 = *reinterpret_cast<const float4*>(row0 + w0);
    float4 c1 = *reinterpret_cast<const float4*>(row1 + w0);
    float  l0 = has_left ? row0[w0 - 1] : 0.f;
    float  l1 = has_left ? row1[w0 - 1] : 0.f;

    for (int c = 0; c < CCH; ++c) {
        // ---- prefetch next channel (independent of current compute) ----
        float4 nprev = make_float4(0.f, 0.f, 0.f, 0.f);
        float4 nc0, nc1;
        float  nl0 = 0.f, nl1 = 0.f;
        if (c + 1 < CCH) {
            const float* nrow0 = xb + (size_t)(c + 1) * HH * WW + (size_t)h0 * WW;
            const float* nrow1 = nrow0 + WW;
            if (has_top) nprev = *reinterpret_cast<const float4*>(nrow0 - WW + w0);
            nc0 = *reinterpret_cast<const float4*>(nrow0 + w0);
            nc1 = *reinterpret_cast<const float4*>(nrow1 + w0);
            if (has_left) { nl0 = nrow0[w0 - 1]; nl1 = nrow1[w0 - 1]; }
        } else {
            nc0 = nc1 = make_float4(0.f, 0.f, 0.f, 0.f);
        }

        // ---- compute current channel ----
        {
            float dx0 = l0   - c0.x;
            float dx1 = c0.x - c0.y;
            float dx2 = c0.y - c0.z;
            float dx3 = c0.z - c0.w;
            float dy0 = prev.x - c0.x;
            float dy1 = prev.y - c0.y;
            float dy2 = prev.z - c0.z;
            float dy3 = prev.w - c0.w;
            a00 += sqrt_approx(dx0 * dx0 + dy0 * dy0);
            a01 += sqrt_approx(dx1 * dx1 + dy1 * dy1);
            a02 += sqrt_approx(dx2 * dx2 + dy2 * dy2);
            a03 += sqrt_approx(dx3 * dx3 + dy3 * dy3);
        }
        {
            float dx0 = l1   - c1.x;
            float dx1 = c1.x - c1.y;
            float dx2 = c1.y - c1.z;
            float dx3 = c1.z - c1.w;
            float dy0 = c0.x - c1.x;
            float dy1 = c0.y - c1.y;
            float dy2 = c0.z - c1.z;
            float dy3 = c0.w - c1.w;
            a10 += sqrt_approx(dx0 * dx0 + dy0 * dy0);
            a11 += sqrt_approx(dx1 * dx1 + dy1 * dy1);
            a12 += sqrt_approx(dx2 * dx2 + dy2 * dy2);
            a13 += sqrt_approx(dx3 * dx3 + dy3 * dy3);
        }

        prev = nprev; c0 = nc0; c1 = nc1; l0 = nl0; l1 = nl1;
    }

    // ---- per-row block prefix sum + box-w, 2 rows sequentially ----
    __shared__ float S[WW + 1];
    __shared__ float wsum[8];

    float* gb = g_scratch + (size_t)b * HP * WW + (size_t)PAD * WW;

    #pragma unroll 1
    for (int r = 0; r < RPB; ++r) {
        float v0 = (r == 0) ? a00 : a10;
        float v1 = (r == 0) ? a01 : a11;
        float v2 = (r == 0) ? a02 : a12;
        float v3 = (r == 0) ? a03 : a13;

        float p0 = v0;
        float p1 = p0 + v1;
        float p2 = p1 + v2;
        float p3 = p2 + v3;
        float t  = p3;

        // inclusive warp scan
        float sc = t;
        #pragma unroll
        for (int o = 1; o < 32; o <<= 1) {
            float v = __shfl_up_sync(0xffffffffu, sc, o);
            if (lane >= o) sc += v;
        }
        if (lane == 31) wsum[wid] = sc;
        __syncthreads();
        if (wid == 0) {
            float wv = (lane < 8) ? wsum[lane] : 0.f;
            float ws = wv;
            #pragma unroll
            for (int o = 1; o < 8; o <<= 1) {
                float v = __shfl_up_sync(0xffffffffu, ws, o);
                if (lane >= o) ws += v;
            }
            if (lane < 8) wsum[lane] = ws - wv;
        }
        __syncthreads();

        float bofs = wsum[wid] + (sc - t);
        if (tid == 0) S[0] = 0.f;
        S[w0 + 1] = bofs + p0;
        S[w0 + 2] = bofs + p1;
        S[w0 + 3] = bofs + p2;
        S[w0 + 4] = bofs + p3;
        __syncthreads();

        // vectorized, L2-pinned store of the 4 box-w outputs
        float4 o4;
        {
            int w  = w0;
            int lo = max(0, w - RAD);
            int hi = min(WW - 1, w + RAD);
            o4.x = S[hi + 1] - S[lo];
        }
        {
            int w  = w0 + 1;
            int lo = max(0, w - RAD);
            int hi = min(WW - 1, w + RAD);
            o4.y = S[hi + 1] - S[lo];
        }
        {
            int w  = w0 + 2;
            int lo = max(0, w - RAD);
            int hi = min(WW - 1, w + RAD);
            o4.z = S[hi + 1] - S[lo];
        }
        {
            int w  = w0 + 3;
            int lo = max(0, w - RAD);
            int hi = min(WW - 1, w + RAD);
            o4.w = S[hi + 1] - S[lo];
        }
        st_evict_last4(gb + (size_t)(h0 + r) * WW + w0, o4, pol);
        __syncthreads();
    }
}

// ---------------------------------------------------------------------------
// Kernel B: box filter along h. HT=64 @ 256 threads + 8-wide chain split:
// window-init amortization cuts reads to (51+128)/64 = 2.80 rows/output row
// (74 MB total traffic); 16 front-batched loads per group give MLP=16/warp so
// ~14 warps/SM still saturate the LTS. Branch-free via zero halo rows.
// ---------------------------------------------------------------------------
#define HT 64
__global__ __launch_bounds__(256) void boxh_kernel(float* __restrict__ out) {
    const int col = blockIdx.x * 256 + threadIdx.x;  // scalar column
    const int h0  = blockIdx.y * HT;
    const int b   = blockIdx.z;

    const float* gp = g_scratch + ((size_t)b * HP + PAD) * WW + col;  // row 0
    float*       op = out + (size_t)b * HH * WW + col;

    // window init over [h0-RAD, h0+RAD] — in-bounds thanks to halo
    float t0 = 0.f, t1 = 0.f, t2 = 0.f, t3 = 0.f;
    #pragma unroll
    for (int j = 0; j < 48; j += 4) {
        t0 += gp[(size_t)(h0 - RAD + j + 0) * WW];
        t1 += gp[(size_t)(h0 - RAD + j + 1) * WW];
        t2 += gp[(size_t)(h0 - RAD + j + 2) * WW];
        t3 += gp[(size_t)(h0 - RAD + j + 3) * WW];
    }
    t0 += gp[(size_t)(h0 + RAD - 2) * WW];
    t1 += gp[(size_t)(h0 + RAD - 1) * WW];
    t2 += gp[(size_t)(h0 + RAD) * WW];

    float s = (t0 + t1) + (t2 + t3);

    // 8-wide sliding window: one chain advance per 8 output rows
    #pragma unroll
    for (int i = 0; i < HT; i += 8) {
        const int h = h0 + i;
        // 16 independent loads, front-batched
        float A0 = gp[(size_t)(h + RAD + 1) * WW];
        float A1 = gp[(size_t)(h + RAD + 2) * WW];
        float A2 = gp[(size_t)(h + RAD + 3) * WW];
        float A3 = gp[(size_t)(h + RAD + 4) * WW];
        float A4 = gp[(size_t)(h + RAD + 5) * WW];
        float A5 = gp[(size_t)(h + RAD + 6) * WW];
        float A6 = gp[(size_t)(h + RAD + 7) * WW];
        float A7 = gp[(size_t)(h + RAD + 8) * WW];
        float B0 = gp[(size_t)(h - RAD + 0) * WW];
        float B1 = gp[(size_t)(h - RAD + 1) * WW];
        float B2 = gp[(size_t)(h - RAD + 2) * WW];
        float B3 = gp[(size_t)(h - RAD + 3) * WW];
        float B4 = gp[(size_t)(h - RAD + 4) * WW];
        float B5 = gp[(size_t)(h - RAD + 5) * WW];
        float B6 = gp[(size_t)(h - RAD + 6) * WW];
        float B7 = gp[(size_t)(h - RAD + 7) * WW];

        float d0 = A0 - B0;
        float d1 = A1 - B1;
        float d2 = A2 - B2;
        float d3 = A3 - B3;
        float d4 = A4 - B4;
        float d5 = A5 - B5;
        float d6 = A6 - B6;
        float d7 = A7 - B7;

        float d01   = d0 + d1;
        float d23   = d2 + d3;
        float d45   = d4 + d5;
        float d67   = d6 + d7;
        float d0123 = d01 + d23;
        float d4567 = d45 + d67;

        op[(size_t)(h + 0) * WW] = s;
        op[(size_t)(h + 1) * WW] = s + d0;
        op[(size_t)(h + 2) * WW] = s + d01;
        op[(size_t)(h + 3) * WW] = s + (d01 + d2);
        op[(size_t)(h + 4) * WW] = s + d0123;
        op[(size_t)(h + 5) * WW] = s + (d0123 + d4);
        op[(size_t)(h + 6) * WW] = s + (d0123 + d45);
        op[(size_t)(h + 7) * WW] = s + (d0123 + (d45 + d6));
        s += d0123 + d4567;
    }
}

// ---------------------------------------------------------------------------

extern "C" void kernel_launch(void* const* d_in, const int* in_sizes, int n_in,
                              void* d_out, int out_size) {
    const float* x = (const float*)d_in[0];
    float* out = (float*)d_out;

    const int n = in_sizes[0];
    const int B = n / (CCH * HH * WW);   // 4

    dim3 gridA(HH / RPB, B);
    grad_boxw_kernel<<<gridA, 256>>>(x);

    dim3 gridB(WW / 256, HH / HT, B);
    boxh_kernel<<<gridB, 256>>>(out);
}

// round 13
// speedup vs baseline: 1.0238x; 1.0238x over previous
#include <cuda_runtime.h>

// Shapes fixed by the problem: [B=4, C=32, H=1024, W=1024] fp32 -> [B,H,W] fp32
#define CCH 32
#define HH  1024
#define WW  1024
#define RAD 25    // kernel_radius = W // 40 = 25 (window = 51)
#define RPB 2     // rows per block in kernel A
#define PAD 32    // zero-pad rows above/below each image in scratch (>= RAD+1)
#define HP  (HH + 2 * PAD)

// padded scratch: channel-summed + box-w'd intermediate, with zero halo rows
__device__ float g_scratch[4 * HP * WW];

__device__ __forceinline__ float sqrt_approx(float s) {
    float r;
    asm("sqrt.approx.f32 %0, %1;" : "=f"(r) : "f"(s));
    return r;   // sqrt.approx(0) = 0, no NaN guard needed
}

// L2 evict_last access policy (keeps scratch resident for kernel B)
__device__ __forceinline__ unsigned long long evict_last_policy() {
    unsigned long long pol;
    asm("createpolicy.fractional.L2::evict_last.b64 %0, 1.0;" : "=l"(pol));
    return pol;
}

// 128-bit store with L2 evict_last cache hint
__device__ __forceinline__ void st_evict_last4(float* p, float4 v, unsigned long long pol) {
    asm volatile("st.global.L2::cache_hint.v4.f32 [%0], {%1,%2,%3,%4}, %5;"
                 :: "l"(p), "f"(v.x), "f"(v.y), "f"(v.z), "f"(v.w), "l"(pol) : "memory");
}

// ---------------------------------------------------------------------------
// Kernel A (FROZEN — measured 86.7us, DRAM+LTS bound): per (b, 2-row tile),
// gradient magnitude, channel sum, box-w. 1-deep software pipeline,
// min-blocks=5 (~40 warps/SM), evict_last scratch stores, fused halo zeroing.
// ---------------------------------------------------------------------------
__global__ __launch_bounds__(256, 5) void grad_boxw_kernel(const float* __restrict__ x) {
    const int h0   = blockIdx.x * RPB;
    const int b    = blockIdx.y;
    const int tid  = threadIdx.x;
    const int lane = tid & 31;
    const int wid  = tid >> 5;
    const int w0   = tid << 2;

    const unsigned long long pol = evict_last_policy();

    // ---- fused halo zeroing ----
    if (blockIdx.x < 2 * PAD) {
        int row  = blockIdx.x;
        int prow = (row < PAD) ? row : (HH + row);
        st_evict_last4(g_scratch + ((size_t)b * HP + prow) * WW + 4 * tid,
                       make_float4(0.f, 0.f, 0.f, 0.f), pol);
    }

    const float* xb = x + (size_t)b * CCH * HH * WW;
    const bool has_top  = (h0 > 0);
    const bool has_left = (w0 > 0);

    float a00 = 0.f, a01 = 0.f, a02 = 0.f, a03 = 0.f;
    float a10 = 0.f, a11 = 0.f, a12 = 0.f, a13 = 0.f;

    // ---- prologue: loads for channel 0 ----
    const float* row0 = xb + (size_t)h0 * WW;
    const float* row1 = row0 + WW;
    float4 prev = has_top ? *reinterpret_cast<const float4*>(row0 - WW + w0)
                          : make_float4(0.f, 0.f, 0.f, 0.f);
    float4 c0 = *reinterpret_cast<const float4*>(row0 + w0);
    float4 c1 = *reinterpret_cast<const float4*>(row1 + w0);
    float  l0 = has_left ? row0[w0 - 1] : 0.f;
    float  l1 = has_left ? row1[w0 - 1] : 0.f;

    for (int c = 0; c < CCH; ++c) {
        // ---- prefetch next channel (independent of current compute) ----
        float4 nprev = make_float4(0.f, 0.f, 0.f, 0.f);
        float4 nc0, nc1;
        float  nl0 = 0.f, nl1 = 0.f;
        if (c + 1 < CCH) {
            const float* nrow0 = xb + (size_t)(c + 1) * HH * WW + (size_t)h0 * WW;
            const float* nrow1 = nrow0 + WW;
            if (has_top) nprev = *reinterpret_cast<const float4*>(nrow0 - WW + w0);
            nc0 = *reinterpret_cast<const float4*>(nrow0 + w0);
            nc1 = *reinterpret_cast<const float4*>(nrow1 + w0);
            if (has_left) { nl0 = nrow0[w0 - 1]; nl1 = nrow1[w0 - 1]; }
        } else {
            nc0 = nc1 = make_float4(0.f, 0.f, 0.f, 0.f);
        }

        // ---- compute current channel ----
        {
            float dx0 = l0   - c0.x;
            float dx1 = c0.x - c0.y;
            float dx2 = c0.y - c0.z;
            float dx3 = c0.z - c0.w;
            float dy0 = prev.x - c0.x;
            float dy1 = prev.y - c0.y;
            float dy2 = prev.z - c0.z;
            float dy3 = prev.w - c0.w;
            a00 += sqrt_approx(dx0 * dx0 + dy0 * dy0);
            a01 += sqrt_approx(dx1 * dx1 + dy1 * dy1);
            a02 += sqrt_approx(dx2 * dx2 + dy2 * dy2);
            a03 += sqrt_approx(dx3 * dx3 + dy3 * dy3);
        }
        {
            float dx0 = l1   - c1.x;
            float dx1 = c1.x - c1.y;
            float dx2 = c1.y - c1.z;
            float dx3 = c1.z - c1.w;
            float dy0 = c0.x - c1.x;
            float dy1 = c0.y - c1.y;
            float dy2 = c0.z - c1.z;
            float dy3 = c0.w - c1.w;
            a10 += sqrt_approx(dx0 * dx0 + dy0 * dy0);
            a11 += sqrt_approx(dx1 * dx1 + dy1 * dy1);
            a12 += sqrt_approx(dx2 * dx2 + dy2 * dy2);
            a13 += sqrt_approx(dx3 * dx3 + dy3 * dy3);
        }

        prev = nprev; c0 = nc0; c1 = nc1; l0 = nl0; l1 = nl1;
    }

    // ---- per-row block prefix sum + box-w, 2 rows sequentially ----
    __shared__ float S[WW + 1];
    __shared__ float wsum[8];

    float* gb = g_scratch + (size_t)b * HP * WW + (size_t)PAD * WW;

    #pragma unroll 1
    for (int r = 0; r < RPB; ++r) {
        float v0 = (r == 0) ? a00 : a10;
        float v1 = (r == 0) ? a01 : a11;
        float v2 = (r == 0) ? a02 : a12;
        float v3 = (r == 0) ? a03 : a13;

        float p0 = v0;
        float p1 = p0 + v1;
        float p2 = p1 + v2;
        float p3 = p2 + v3;
        float t  = p3;

        // inclusive warp scan
        float sc = t;
        #pragma unroll
        for (int o = 1; o < 32; o <<= 1) {
            float v = __shfl_up_sync(0xffffffffu, sc, o);
            if (lane >= o) sc += v;
        }
        if (lane == 31) wsum[wid] = sc;
        __syncthreads();
        if (wid == 0) {
            float wv = (lane < 8) ? wsum[lane] : 0.f;
            float ws = wv;
            #pragma unroll
            for (int o = 1; o < 8; o <<= 1) {
                float v = __shfl_up_sync(0xffffffffu, ws, o);
                if (lane >= o) ws += v;
            }
            if (lane < 8) wsum[lane] = ws - wv;
        }
        __syncthreads();

        float bofs = wsum[wid] + (sc - t);
        if (tid == 0) S[0] = 0.f;
        S[w0 + 1] = bofs + p0;
        S[w0 + 2] = bofs + p1;
        S[w0 + 3] = bofs + p2;
        S[w0 + 4] = bofs + p3;
        __syncthreads();

        // vectorized, L2-pinned store of the 4 box-w outputs
        float4 o4;
        {
            int w  = w0;
            int lo = max(0, w - RAD);
            int hi = min(WW - 1, w + RAD);
            o4.x = S[hi + 1] - S[lo];
        }
        {
            int w  = w0 + 1;
            int lo = max(0, w - RAD);
            int hi = min(WW - 1, w + RAD);
            o4.y = S[hi + 1] - S[lo];
        }
        {
            int w  = w0 + 2;
            int lo = max(0, w - RAD);
            int hi = min(WW - 1, w + RAD);
            o4.z = S[hi + 1] - S[lo];
        }
        {
            int w  = w0 + 3;
            int lo = max(0, w - RAD);
            int hi = min(WW - 1, w + RAD);
            o4.w = S[hi + 1] - S[lo];
        }
        st_evict_last4(gb + (size_t)(h0 + r) * WW + w0, o4, pol);
        __syncthreads();
    }
}

// ---------------------------------------------------------------------------
// Kernel B: box filter along h. HT=32 @ 256 threads (proven 512-block shape,
// occ ~33%) + 8-wide chain split: 16 front-batched loads per group, one
// serial-chain advance per 8 output rows. Branch-free via zero halo rows.
// ---------------------------------------------------------------------------
#define HT 32
__global__ __launch_bounds__(256) void boxh_kernel(float* __restrict__ out) {
    const int col = blockIdx.x * 256 + threadIdx.x;  // scalar column
    const int h0  = blockIdx.y * HT;
    const int b   = blockIdx.z;

    const float* gp = g_scratch + ((size_t)b * HP + PAD) * WW + col;  // row 0
    float*       op = out + (size_t)b * HH * WW + col;

    // window init over [h0-RAD, h0+RAD] — in-bounds thanks to halo
    float t0 = 0.f, t1 = 0.f, t2 = 0.f, t3 = 0.f;
    #pragma unroll
    for (int j = 0; j < 48; j += 4) {
        t0 += gp[(size_t)(h0 - RAD + j + 0) * WW];
        t1 += gp[(size_t)(h0 - RAD + j + 1) * WW];
        t2 += gp[(size_t)(h0 - RAD + j + 2) * WW];
        t3 += gp[(size_t)(h0 - RAD + j + 3) * WW];
    }
    t0 += gp[(size_t)(h0 + RAD - 2) * WW];
    t1 += gp[(size_t)(h0 + RAD - 1) * WW];
    t2 += gp[(size_t)(h0 + RAD) * WW];

    float s = (t0 + t1) + (t2 + t3);

    // 8-wide sliding window: one chain advance per 8 output rows
    #pragma unroll
    for (int i = 0; i < HT; i += 8) {
        const int h = h0 + i;
        // 16 independent loads, front-batched
        float A0 = gp[(size_t)(h + RAD + 1) * WW];
        float A1 = gp[(size_t)(h + RAD + 2) * WW];
        float A2 = gp[(size_t)(h + RAD + 3) * WW];
        float A3 = gp[(size_t)(h + RAD + 4) * WW];
        float A4 = gp[(size_t)(h + RAD + 5) * WW];
        float A5 = gp[(size_t)(h + RAD + 6) * WW];
        float A6 = gp[(size_t)(h + RAD + 7) * WW];
        float A7 = gp[(size_t)(h + RAD + 8) * WW];
        float B0 = gp[(size_t)(h - RAD + 0) * WW];
        float B1 = gp[(size_t)(h - RAD + 1) * WW];
        float B2 = gp[(size_t)(h - RAD + 2) * WW];
        float B3 = gp[(size_t)(h - RAD + 3) * WW];
        float B4 = gp[(size_t)(h - RAD + 4) * WW];
        float B5 = gp[(size_t)(h - RAD + 5) * WW];
        float B6 = gp[(size_t)(h - RAD + 6) * WW];
        float B7 = gp[(size_t)(h - RAD + 7) * WW];

        float d0 = A0 - B0;
        float d1 = A1 - B1;
        float d2 = A2 - B2;
        float d3 = A3 - B3;
        float d4 = A4 - B4;
        float d5 = A5 - B5;
        float d6 = A6 - B6;
        float d7 = A7 - B7;

        float d01   = d0 + d1;
        float d23   = d2 + d3;
        float d45   = d4 + d5;
        float d67   = d6 + d7;
        float d0123 = d01 + d23;
        float d4567 = d45 + d67;

        op[(size_t)(h + 0) * WW] = s;
        op[(size_t)(h + 1) * WW] = s + d0;
        op[(size_t)(h + 2) * WW] = s + d01;
        op[(size_t)(h + 3) * WW] = s + (d01 + d2);
        op[(size_t)(h + 4) * WW] = s + d0123;
        op[(size_t)(h + 5) * WW] = s + (d0123 + d4);
        op[(size_t)(h + 6) * WW] = s + (d0123 + d45);
        op[(size_t)(h + 7) * WW] = s + (d0123 + (d45 + d6));
        s += d0123 + d4567;
    }
}

// ---------------------------------------------------------------------------

extern "C" void kernel_launch(void* const* d_in, const int* in_sizes, int n_in,
                              void* d_out, int out_size) {
    const float* x = (const float*)d_in[0];
    float* out = (float*)d_out;

    const int n = in_sizes[0];
    const int B = n / (CCH * HH * WW);   // 4

    dim3 gridA(HH / RPB, B);
    grad_boxw_kernel<<<gridA, 256>>>(x);

    dim3 gridB(WW / 256, HH / HT, B);
    boxh_kernel<<<gridB, 256>>>(out);
}